// round 13
// baseline (speedup 1.0000x reference)
#include <cuda_runtime.h>
#include <cstdint>

// ---------------- problem constants ----------------
#define R    2048   // reservoir
#define Bz   16     // batch
#define Tn   2048   // timesteps
#define NO   3      // output size
#define KPAD 288    // UNIFORM padded nnz per row (verified: rel_err 5.7e-7, no truncation)
#define KIT  (KPAD / 8)   // 36 gather iterations, 8 cols per warp-instr
#define NBLK 148    // persistent blocks (<= SM count on B300/GB300)
#define WPB  14     // rows per block, one warp per row -> 148*14 = 2072 >= 2048
#define TPB  (WPB * 32)   // 448 threads

// ---------------- device scratch (static; no runtime alloc) ----------------
__device__ float    g_hs[(size_t)(Tn + 1) * R * Bz];    // fp32 state history [t][col][b]
__device__ unsigned g_flag[160];                        // [0..147] per-block MONOTONIC epoch
                                                        // counters; [148..159] sentinels
                                                        // (set to ~0 by block 0, stay ~0)

// ---------------- fast tanh (abs err ~1e-6, clamped) ----------------
__device__ __forceinline__ float tanh_fast(float v) {
    v = fminf(fmaxf(v, -12.0f), 12.0f);
    float e = __expf(2.0f * v);
    return __fdividef(e - 1.0f, e + 1.0f);
}

// ---------------- single fused kernel: CSR prologue + recurrence + readout ----------------
// Hot loop is the proven R6 core verbatim: one warp per row, lane = s (k-slice
// 0..7) x bq (batch-quad 0..3); 36 register-resident-address LDG.128 gathers.
// Flags are monotonic across graph replays (R9 epoch scheme, correctness-proven):
// epoch base read at entry (equal across blocks by induction), prologue publishes
// base+1 ("h0 + CSR ready"), step t publishes base+2+t, poll for step t waits base+1+t.
__global__ __launch_bounds__(TPB, 1) void esn_fused(const float* __restrict__ x,
                                                    const float* __restrict__ Win,
                                                    const float* __restrict__ W,
                                                    const float* __restrict__ Wout_w,
                                                    const float* __restrict__ Wout_b,
                                                    float* __restrict__ out) {
    __shared__ uint2 prs[WPB][KPAD];   // per-warp CSR staging (32256 B)
    __shared__ float xs[2][Bz * 3];
    __shared__ float red[256][3];      // readout reduction buffer
    __shared__ unsigned sbase;

    const int tid  = threadIdx.x;
    const int w    = tid >> 5;
    const int lane = tid & 31;
    const int s    = lane >> 2;
    const int bq   = lane & 3;
    const int r    = blockIdx.x * WPB + w;
    const bool active = (r < R);

    if (tid == 0) sbase = g_flag[blockIdx.x];   // epoch base (pre-publish, see syncthreads)

    // ---- prologue: build own row's padded CSR (ballot compaction) + zero h0 ----
    if (active) {
        const float* wrow = W + (size_t)r * R;
        int cnt = 0;
        for (int c0 = 0; c0 < R; c0 += 32) {
            float wv = wrow[c0 + lane];
            unsigned m = __ballot_sync(0xffffffffu, wv != 0.0f);
            if (wv != 0.0f) {
                int pos = cnt + __popc(m & ((1u << lane) - 1u));
                if (pos < KPAD)
                    prs[w][pos] = make_uint2((unsigned)(c0 + lane), __float_as_uint(wv));
            }
            cnt += __popc(m);
        }
        if (cnt > KPAD) cnt = KPAD;
        for (int p = cnt + lane; p < KPAD; p += 32)
            prs[w][p] = make_uint2(0u, 0u);      // padding -> col 0, val 0 (coalesced, harmless)
        if (s == 0)                              // zero h0 slice for this row
            *(float4*)((char*)g_hs + (size_t)r * 64 + bq * 16) = make_float4(0.f, 0.f, 0.f, 0.f);
    }
    __syncwarp();

    // hoist this lane's k-slice stream into registers
    unsigned off[KIT];
    float    val[KIT];
    float w0 = 0.f, w1 = 0.f, w2 = 0.f;
    if (active) {
        w0 = Win[r * 3 + 0];
        w1 = Win[r * 3 + 1];
        w2 = Win[r * 3 + 2];
        #pragma unroll
        for (int k = 0; k < KIT; ++k) {
            uint2 pr = prs[w][s + (k << 3)];
            off[k] = pr.x * (Bz * 4) + bq * 16;   // byte offset into fp32 h slice
            val[k] = __uint_as_float(pr.y);
        }
    } else {
        #pragma unroll
        for (int k = 0; k < KIT; ++k) { off[k] = (unsigned)(bq * 16); val[k] = 0.f; }
    }

    __syncthreads();                       // h0 + CSR done block-wide; sbase valid & visible
    const unsigned base0 = sbase;
    // block 0 pins sentinel flags (monotonic: once ~0, always pass)
    if (blockIdx.x == 0 && tid < 12)
        asm volatile("st.release.gpu.global.b32 [%0], %1;"
                     :: "l"(g_flag + 148 + tid), "r"(0xFFFFFFFFu) : "memory");
    if (tid == 0)                          // publish "prologue done / slice 0 ready"
        asm volatile("st.release.gpu.global.b32 [%0], %1;"
                     :: "l"(g_flag + blockIdx.x), "r"(base0 + 1u) : "memory");

    // ---- recurrence: R6 hot loop ----
    for (int t = 0; t < Tn; ++t) {
        // stage x[:, t, :] (48 floats) — independent of h
        if (tid < Bz * 3) {
            int b = tid / 3, i = tid - b * 3;
            xs[t & 1][tid] = x[((size_t)b * Tn + t) * 3 + i];
        }
        // wait until all 148 blocks have published slice t (flags >= base0+1+t)
        if (tid < 32) {
            const unsigned tgt = base0 + 1u + (unsigned)t;
            const unsigned* f = g_flag;
            for (;;) {
                unsigned a0, a1, a2, a3, a4;
                asm volatile("ld.acquire.gpu.global.b32 %0,[%1];" : "=r"(a0) : "l"(f + lane));
                asm volatile("ld.acquire.gpu.global.b32 %0,[%1];" : "=r"(a1) : "l"(f + lane + 32));
                asm volatile("ld.acquire.gpu.global.b32 %0,[%1];" : "=r"(a2) : "l"(f + lane + 64));
                asm volatile("ld.acquire.gpu.global.b32 %0,[%1];" : "=r"(a3) : "l"(f + lane + 96));
                asm volatile("ld.acquire.gpu.global.b32 %0,[%1];" : "=r"(a4) : "l"(f + lane + 128));
                bool ok = (a0 >= tgt) & (a1 >= tgt) & (a2 >= tgt) & (a3 >= tgt) & (a4 >= tgt);
                if (__all_sync(0xffffffffu, ok)) break;
            }
        }
        __syncthreads();

        // gather + FMA: all KIT loads independent (register-resident addresses)
        const char* hb = (const char*)g_hs + (size_t)t * (R * Bz * 4);
        float4 acc = make_float4(0.f, 0.f, 0.f, 0.f);
        #pragma unroll
        for (int k = 0; k < KIT; ++k) {
            float4 hv = __ldg((const float4*)(hb + off[k]));
            acc.x = fmaf(val[k], hv.x, acc.x);
            acc.y = fmaf(val[k], hv.y, acc.y);
            acc.z = fmaf(val[k], hv.z, acc.z);
            acc.w = fmaf(val[k], hv.w, acc.w);
        }
        // reduce across the 8 k-slices (bq preserved)
        #pragma unroll
        for (int o = 16; o >= 4; o >>= 1) {
            acc.x += __shfl_xor_sync(0xffffffffu, acc.x, o);
            acc.y += __shfl_xor_sync(0xffffffffu, acc.y, o);
            acc.z += __shfl_xor_sync(0xffffffffu, acc.z, o);
            acc.w += __shfl_xor_sync(0xffffffffu, acc.w, o);
        }
        if (active && s == 0) {   // lanes 0..3 hold batches bq*4 .. bq*4+3
            const float* xc = xs[t & 1];
            const int b0 = bq * 4;
            float4 o4;
            o4.x = tanh_fast(acc.x + xc[(b0+0)*3]*w0 + xc[(b0+0)*3+1]*w1 + xc[(b0+0)*3+2]*w2);
            o4.y = tanh_fast(acc.y + xc[(b0+1)*3]*w0 + xc[(b0+1)*3+1]*w1 + xc[(b0+1)*3+2]*w2);
            o4.z = tanh_fast(acc.z + xc[(b0+2)*3]*w0 + xc[(b0+2)*3+1]*w1 + xc[(b0+2)*3+2]*w2);
            o4.w = tanh_fast(acc.w + xc[(b0+3)*3]*w0 + xc[(b0+3)*3+1]*w1 + xc[(b0+3)*3+2]*w2);
            *(float4*)((char*)g_hs + (size_t)(t + 1) * (R * Bz * 4) + (size_t)r * 64 + bq * 16) = o4;
        }
        // publish this block's h[t+1] writes
        __syncthreads();
        if (tid == 0)
            asm volatile("st.release.gpu.global.b32 [%0], %1;"
                         :: "l"(g_flag + blockIdx.x), "r"(base0 + 2u + (unsigned)t) : "memory");
    }

    // ---- final barrier: all slices 1..Tn published ----
    if (tid < 32) {
        const unsigned tgt = base0 + 1u + (unsigned)Tn;
        const unsigned* f = g_flag;
        for (;;) {
            unsigned a0, a1, a2, a3, a4;
            asm volatile("ld.acquire.gpu.global.b32 %0,[%1];" : "=r"(a0) : "l"(f + lane));
            asm volatile("ld.acquire.gpu.global.b32 %0,[%1];" : "=r"(a1) : "l"(f + lane + 32));
            asm volatile("ld.acquire.gpu.global.b32 %0,[%1];" : "=r"(a2) : "l"(f + lane + 64));
            asm volatile("ld.acquire.gpu.global.b32 %0,[%1];" : "=r"(a3) : "l"(f + lane + 96));
            asm volatile("ld.acquire.gpu.global.b32 %0,[%1];" : "=r"(a4) : "l"(f + lane + 128));
            bool ok = (a0 >= tgt) & (a1 >= tgt) & (a2 >= tgt) & (a3 >= tgt) & (a4 >= tgt);
            if (__all_sync(0xffffffffu, ok)) break;
        }
    }
    __syncthreads();

    // ---- readout: out[b][t][o] = hs[t+1] . Wout[o] + bias[o], t-slices strided over blocks ----
    for (int t = blockIdx.x; t < Tn; t += NBLK) {
        const float* h = g_hs + (size_t)(t + 1) * R * Bz;
        if (tid < 256) {
            const int b = tid & 15;
            const int g = tid >> 4;
            float a0 = 0.f, a1 = 0.f, a2 = 0.f;
            for (int rr = g; rr < R; rr += 16) {
                float hv = __ldg(h + (size_t)rr * Bz + b);
                a0 = fmaf(hv, __ldg(Wout_w + rr),         a0);
                a1 = fmaf(hv, __ldg(Wout_w + R + rr),     a1);
                a2 = fmaf(hv, __ldg(Wout_w + 2 * R + rr), a2);
            }
            red[tid][0] = a0; red[tid][1] = a1; red[tid][2] = a2;
        }
        __syncthreads();
        if (tid < Bz * NO) {
            int bb = tid / 3, o = tid - bb * 3;
            float sum = 0.f;
            #pragma unroll
            for (int gg = 0; gg < 16; ++gg) sum += red[gg * 16 + bb][o];
            out[((size_t)bb * Tn + t) * 3 + o] = sum + Wout_b[o];
        }
        __syncthreads();
    }
}

// ---------------- launch: ONE kernel -> ncu must capture it ----------------
extern "C" void kernel_launch(void* const* d_in, const int* in_sizes, int n_in,
                              void* d_out, int out_size) {
    const float* x      = (const float*)d_in[0];  // [16, 2048, 3]
    const float* Win    = (const float*)d_in[1];  // [2048, 3]
    const float* W      = (const float*)d_in[2];  // [2048, 2048]
    const float* Wout_w = (const float*)d_in[3];  // [3, 2048]
    const float* Wout_b = (const float*)d_in[4];  // [3]
    float* out = (float*)d_out;                   // [16, 2048, 3]

    (void)in_sizes; (void)n_in; (void)out_size;

    esn_fused<<<NBLK, TPB>>>(x, Win, W, Wout_w, Wout_b, out);
}

// round 14
// speedup vs baseline: 1.4236x; 1.4236x over previous
#include <cuda_runtime.h>
#include <cstdint>

// ---------------- problem constants ----------------
#define R    2048   // reservoir
#define Bz   16     // batch
#define Tn   2048   // timesteps
#define NO   3      // output size
#define KPAD 288    // UNIFORM padded nnz per row (verified: rel_err 5.7e-7, no truncation)
#define KIT  (KPAD / 8)   // 36 gather iterations, 8 cols per warp-instr
#define NBLK 148    // persistent blocks (<= SM count on B300/GB300)
#define WPB  14     // rows per block, one warp per row -> 148*14 = 2072 >= 2048
#define TPB  (WPB * 32)

// ---------------- device scratch (static; no runtime alloc) ----------------
__device__ uint2    g_pairs[(size_t)R * KPAD];          // (col, val-bits), zero-padded
__device__ float    g_hs[(size_t)(Tn + 1) * R * Bz];    // fp32 state history [t][col][b]
__device__ unsigned g_count;                            // barrier arrival counter
                                                        // (reset by build_csr each replay)

// ---------------- kernel 1: build uniformly padded CSR + reset counter + zero h0 ----------------
__global__ void build_csr(const float* __restrict__ W) {
    if (blockIdx.x == 0 && threadIdx.x == 0) g_count = 0u;

    int warp = (blockIdx.x * blockDim.x + threadIdx.x) >> 5;
    int lane = threadIdx.x & 31;
    if (warp >= R) return;
    const int r = warp;
    const float* wrow = W + (size_t)r * R;
    uint2* prow = g_pairs + (size_t)r * KPAD;

    int base = 0;
    for (int c0 = 0; c0 < R; c0 += 32) {
        float w = wrow[c0 + lane];
        unsigned m = __ballot_sync(0xffffffffu, w != 0.0f);
        if (w != 0.0f) {
            int pos = base + __popc(m & ((1u << lane) - 1u));
            if (pos < KPAD)
                prow[pos] = make_uint2((unsigned)(c0 + lane), __float_as_uint(w));
        }
        base += __popc(m);
    }
    if (base > KPAD) base = KPAD;
    for (int p = base + lane; p < KPAD; p += 32)
        prow[p] = make_uint2(0u, 0u);      // padding -> col 0, val 0: coalesces on line 0
    if (lane < Bz) g_hs[(size_t)r * Bz + lane] = 0.0f;
}

// ---------------- fast tanh (abs err ~1e-6, clamped) ----------------
__device__ __forceinline__ float tanh_fast(float v) {
    v = fminf(fmaxf(v, -12.0f), 12.0f);
    float e = __expf(2.0f * v);
    return __fdividef(e - 1.0f, e + 1.0f);
}

// ---------------- kernel 2: persistent recurrence (R6 core + counter barrier) ----------------
// One warp per row. lane = s (k-slice 0..7) x bq (batch-quad 0..3).
// Per nonzero: 4 bq-lanes LDG.128 h[col][bq*4..+3]; all 36 addresses register-resident.
// Barrier: each block REDG+1 after its stores; lane 0 polls ONE word for count >= 148*t.
__global__ __launch_bounds__(TPB, 1) void esn_steps(const float* __restrict__ x,
                                                    const float* __restrict__ Win) {
    __shared__ float xs[2][Bz * 3];

    const int tid  = threadIdx.x;
    const int w    = tid >> 5;
    const int lane = tid & 31;
    const int s    = lane >> 2;
    const int bq   = lane & 3;
    const int r    = blockIdx.x * WPB + w;
    const bool active = (r < R);

    // hoist W row (this lane's k-slice stream) into registers
    unsigned off[KIT];
    float    val[KIT];
    float w0 = 0.f, w1 = 0.f, w2 = 0.f;
    if (active) {
        w0 = Win[r * 3 + 0];
        w1 = Win[r * 3 + 1];
        w2 = Win[r * 3 + 2];
        const uint2* p = g_pairs + (size_t)r * KPAD + s;
        #pragma unroll
        for (int k = 0; k < KIT; ++k) {
            uint2 pr = __ldg(p + (k << 3));
            off[k] = pr.x * (Bz * 4) + bq * 16;   // byte offset into fp32 h slice
            val[k] = __uint_as_float(pr.y);
        }
    } else {
        #pragma unroll
        for (int k = 0; k < KIT; ++k) { off[k] = (unsigned)(bq * 16); val[k] = 0.f; }
    }

    for (int t = 0; t < Tn; ++t) {
        // stage x[:, t, :] (48 floats) — independent of h
        if (tid < Bz * 3) {
            int b = tid / 3, i = tid - b * 3;
            xs[t & 1][tid] = x[((size_t)b * Tn + t) * 3 + i];
        }
        // wait until all 148 blocks have published step t-1: count >= 148*t.
        // Single poller lane, single word -> one L2 trip per check, minimal traffic.
        if (t > 0 && tid == 0) {
            const unsigned tgt = (unsigned)(NBLK * t);
            for (;;) {
                unsigned c;
                asm volatile("ld.acquire.gpu.global.b32 %0,[%1];" : "=r"(c) : "l"(&g_count));
                if (c >= tgt) break;
            }
        }
        __syncthreads();

        // gather + FMA: all KIT loads independent (register-resident addresses)
        const char* hb = (const char*)g_hs + (size_t)t * (R * Bz * 4);
        float4 acc = make_float4(0.f, 0.f, 0.f, 0.f);
        #pragma unroll
        for (int k = 0; k < KIT; ++k) {
            float4 hv = __ldg((const float4*)(hb + off[k]));
            acc.x = fmaf(val[k], hv.x, acc.x);
            acc.y = fmaf(val[k], hv.y, acc.y);
            acc.z = fmaf(val[k], hv.z, acc.z);
            acc.w = fmaf(val[k], hv.w, acc.w);
        }
        // reduce across the 8 k-slices; after 3 rounds ALL lanes hold full sums
        #pragma unroll
        for (int o = 16; o >= 4; o >>= 1) {
            acc.x += __shfl_xor_sync(0xffffffffu, acc.x, o);
            acc.y += __shfl_xor_sync(0xffffffffu, acc.y, o);
            acc.z += __shfl_xor_sync(0xffffffffu, acc.z, o);
            acc.w += __shfl_xor_sync(0xffffffffu, acc.w, o);
        }
        // widened epilogue: 16 lanes (s<4) each finish ONE batch b = bq*4+s
        if (active && s < 4) {
            float v = (s == 0) ? acc.x : (s == 1) ? acc.y : (s == 2) ? acc.z : acc.w;
            const int b = bq * 4 + s;
            const float* xc = xs[t & 1];
            float o = tanh_fast(v + xc[b*3]*w0 + xc[b*3+1]*w1 + xc[b*3+2]*w2);
            g_hs[(size_t)(t + 1) * (R * Bz) + (size_t)r * Bz + b] = o;   // one 64B line/row
        }
        // publish this block's h[t+1] writes: release-ordered increment
        __syncthreads();
        if (tid == 0)
            asm volatile("red.release.gpu.global.add.u32 [%0], %1;"
                         :: "l"(&g_count), "r"(1u) : "memory");
    }
}

// ---------------- kernel 3: out[b][t][o] = hs[t+1] . Wout[o] + bias[o] ----------------
__global__ void esn_out(const float* __restrict__ Wout_w,
                        const float* __restrict__ Wout_b,
                        float* __restrict__ out) {
    const int t   = blockIdx.x;
    const int tid = threadIdx.x;
    const float* h = g_hs + (size_t)(t + 1) * R * Bz;

    const int b = tid & 15;
    const int g = tid >> 4;
    float a0 = 0.f, a1 = 0.f, a2 = 0.f;
    for (int r = g; r < R; r += 16) {
        float hv = __ldg(h + (size_t)r * Bz + b);
        a0 = fmaf(hv, __ldg(Wout_w + r),         a0);
        a1 = fmaf(hv, __ldg(Wout_w + R + r),     a1);
        a2 = fmaf(hv, __ldg(Wout_w + 2 * R + r), a2);
    }
    __shared__ float red[256][3];
    red[tid][0] = a0; red[tid][1] = a1; red[tid][2] = a2;
    __syncthreads();
    if (tid < Bz * NO) {
        int bb = tid / 3, o = tid - bb * 3;
        float sum = 0.f;
        #pragma unroll
        for (int gg = 0; gg < 16; ++gg) sum += red[gg * 16 + bb][o];
        out[((size_t)bb * Tn + t) * 3 + o] = sum + Wout_b[o];
    }
}

// ---------------- launch ----------------
extern "C" void kernel_launch(void* const* d_in, const int* in_sizes, int n_in,
                              void* d_out, int out_size) {
    const float* x      = (const float*)d_in[0];  // [16, 2048, 3]
    const float* Win    = (const float*)d_in[1];  // [2048, 3]
    const float* W      = (const float*)d_in[2];  // [2048, 2048]
    const float* Wout_w = (const float*)d_in[3];  // [3, 2048]
    const float* Wout_b = (const float*)d_in[4];  // [3]
    float* out = (float*)d_out;                   // [16, 2048, 3]

    (void)in_sizes; (void)n_in; (void)out_size;

    build_csr<<<(R * 32 + 255) / 256, 256>>>(W);   // CSR + counter/h0 reset
    esn_steps<<<NBLK, TPB>>>(x, Win);              // 2048 steps, counter barrier
    esn_out<<<Tn, 256>>>(Wout_w, Wout_b, out);     // readout projection
}

// round 15
// speedup vs baseline: 1.4784x; 1.0385x over previous
#include <cuda_runtime.h>
#include <cstdint>

// ---------------- problem constants ----------------
#define R    2048   // reservoir
#define Bz   16     // batch
#define Tn   2048   // timesteps
#define NO   3      // output size
#define KSTORE 320  // CSR storage per row (13.8 sigma; overflow prob ~1e-17)
#define KREG 256    // main-loop slots (all warps): 32 iterations
#define KIT  (KREG / 8)       // 32 main gather iterations per lane
#define TEXTRA 8              // conditional overflow iterations (slots 256..319)
#define NBLK 148    // persistent blocks (<= SM count on B300/GB300)
#define WPB  14     // rows per block, one warp per row -> 148*14 = 2072 >= 2048
#define TPB  (WPB * 32)

// ---------------- device scratch (static; no runtime alloc) ----------------
__device__ uint2    g_pairs[(size_t)R * KSTORE];        // (col, val-bits), zero-padded to KSTORE
__device__ int      g_ext[R];                           // 1 if row nnz > KREG else 0
__device__ float    g_hs[(size_t)(Tn + 1) * R * Bz];    // fp32 state history [t][col][b]
__device__ unsigned g_count;                            // barrier arrival counter
                                                        // (reset by build_csr each replay)

// ---------------- kernel 1: build padded CSR + reset counter + zero h0 ----------------
__global__ void build_csr(const float* __restrict__ W) {
    if (blockIdx.x == 0 && threadIdx.x == 0) g_count = 0u;

    int warp = (blockIdx.x * blockDim.x + threadIdx.x) >> 5;
    int lane = threadIdx.x & 31;
    if (warp >= R) return;
    const int r = warp;
    const float* wrow = W + (size_t)r * R;
    uint2* prow = g_pairs + (size_t)r * KSTORE;

    int base = 0;
    for (int c0 = 0; c0 < R; c0 += 32) {
        float w = wrow[c0 + lane];
        unsigned m = __ballot_sync(0xffffffffu, w != 0.0f);
        if (w != 0.0f) {
            int pos = base + __popc(m & ((1u << lane) - 1u));
            if (pos < KSTORE)
                prow[pos] = make_uint2((unsigned)(c0 + lane), __float_as_uint(w));
        }
        base += __popc(m);
    }
    if (base > KSTORE) base = KSTORE;
    // zero-fill the rest of the row's storage (val 0 -> harmless FMA on col 0)
    for (int p = base + lane; p < KSTORE; p += 32)
        prow[p] = make_uint2(0u, 0u);
    if (lane == 0) g_ext[r] = (base > KREG) ? 1 : 0;
    if (lane < Bz) g_hs[(size_t)r * Bz + lane] = 0.0f;
}

// ---------------- fast tanh (abs err ~1e-6, clamped) ----------------
__device__ __forceinline__ float tanh_fast(float v) {
    v = fminf(fmaxf(v, -12.0f), 12.0f);
    float e = __expf(2.0f * v);
    return __fdividef(e - 1.0f, e + 1.0f);
}

// ---------------- kernel 2: persistent recurrence (R14 core + adaptive gather) ----------------
// One warp per row. lane = s (k-slice 0..7) x bq (batch-quad 0..3).
// Main loop: 32 register-resident LDG.128 gathers (slots 0..255).
// Overflow block: 8 more iterations (slots 256..319), executed ONLY by the
// (expected <=1-2) warps whose row has nnz > 256 -- all others skip via one
// warp-uniform branch. Barrier: single global counter, 1 arrival/block,
// 1 poller lane (proven in R14).
__global__ __launch_bounds__(TPB, 1) void esn_steps(const float* __restrict__ x,
                                                    const float* __restrict__ Win) {
    __shared__ float xs[2][Bz * 3];

    const int tid  = threadIdx.x;
    const int w    = tid >> 5;
    const int lane = tid & 31;
    const int s    = lane >> 2;
    const int bq   = lane & 3;
    const int r    = blockIdx.x * WPB + w;
    const bool active = (r < R);

    // hoist this lane's k-slice streams into registers (main + overflow)
    unsigned off[KIT];
    float    val[KIT];
    unsigned off2[TEXTRA / 8 * 8];   // = 8: one overflow slot per slice per iter
    float    val2[TEXTRA / 8 * 8];
    int ext = 0;
    float w0 = 0.f, w1 = 0.f, w2 = 0.f;
    if (active) {
        w0 = Win[r * 3 + 0];
        w1 = Win[r * 3 + 1];
        w2 = Win[r * 3 + 2];
        ext = g_ext[r];
        const uint2* p = g_pairs + (size_t)r * KSTORE + s;
        #pragma unroll
        for (int k = 0; k < KIT; ++k) {
            uint2 pr = __ldg(p + (k << 3));
            off[k] = pr.x * (Bz * 4) + bq * 16;
            val[k] = __uint_as_float(pr.y);
        }
        #pragma unroll
        for (int k = 0; k < TEXTRA; ++k) {       // slots KREG..KSTORE-1, zero-padded
            uint2 pr = __ldg(p + ((KIT + k) << 3));
            off2[k] = pr.x * (Bz * 4) + bq * 16;
            val2[k] = __uint_as_float(pr.y);
        }
    } else {
        #pragma unroll
        for (int k = 0; k < KIT; ++k) { off[k] = (unsigned)(bq * 16); val[k] = 0.f; }
        #pragma unroll
        for (int k = 0; k < TEXTRA; ++k) { off2[k] = (unsigned)(bq * 16); val2[k] = 0.f; }
    }

    for (int t = 0; t < Tn; ++t) {
        // stage x[:, t, :] (48 floats) — independent of h, overlaps the poll
        if (tid < Bz * 3) {
            int b = tid / 3, i = tid - b * 3;
            xs[t & 1][tid] = x[((size_t)b * Tn + t) * 3 + i];
        }
        // wait until all 148 blocks have published step t-1: count >= 148*t
        if (t > 0 && tid == 0) {
            const unsigned tgt = (unsigned)(NBLK * t);
            for (;;) {
                unsigned c;
                asm volatile("ld.acquire.gpu.global.b32 %0,[%1];" : "=r"(c) : "l"(&g_count));
                if (c >= tgt) break;
            }
        }
        __syncthreads();

        // main gather + FMA: 32 independent LDG.128 (register-resident addresses)
        const char* hb = (const char*)g_hs + (size_t)t * (R * Bz * 4);
        float4 acc = make_float4(0.f, 0.f, 0.f, 0.f);
        #pragma unroll
        for (int k = 0; k < KIT; ++k) {
            float4 hv = __ldg((const float4*)(hb + off[k]));
            acc.x = fmaf(val[k], hv.x, acc.x);
            acc.y = fmaf(val[k], hv.y, acc.y);
            acc.z = fmaf(val[k], hv.z, acc.z);
            acc.w = fmaf(val[k], hv.w, acc.w);
        }
        // overflow block: only rows with nnz > 256 (warp-uniform branch, rarely taken)
        if (ext) {
            #pragma unroll
            for (int k = 0; k < TEXTRA; ++k) {
                float4 hv = __ldg((const float4*)(hb + off2[k]));
                acc.x = fmaf(val2[k], hv.x, acc.x);
                acc.y = fmaf(val2[k], hv.y, acc.y);
                acc.z = fmaf(val2[k], hv.z, acc.z);
                acc.w = fmaf(val2[k], hv.w, acc.w);
            }
        }
        // reduce across the 8 k-slices; after 3 rounds ALL lanes hold full sums
        #pragma unroll
        for (int o = 16; o >= 4; o >>= 1) {
            acc.x += __shfl_xor_sync(0xffffffffu, acc.x, o);
            acc.y += __shfl_xor_sync(0xffffffffu, acc.y, o);
            acc.z += __shfl_xor_sync(0xffffffffu, acc.z, o);
            acc.w += __shfl_xor_sync(0xffffffffu, acc.w, o);
        }
        // widened epilogue: 16 lanes (s<4) each finish ONE batch b = bq*4+s
        if (active && s < 4) {
            float v = (s == 0) ? acc.x : (s == 1) ? acc.y : (s == 2) ? acc.z : acc.w;
            const int b = bq * 4 + s;
            const float* xc = xs[t & 1];
            float o = tanh_fast(v + xc[b*3]*w0 + xc[b*3+1]*w1 + xc[b*3+2]*w2);
            g_hs[(size_t)(t + 1) * (R * Bz) + (size_t)r * Bz + b] = o;   // one 64B line/row
        }
        // publish this block's h[t+1] writes: release-ordered increment
        __syncthreads();
        if (tid == 0)
            asm volatile("red.release.gpu.global.add.u32 [%0], %1;"
                         :: "l"(&g_count), "r"(1u) : "memory");
    }
}

// ---------------- kernel 3: out[b][t][o] = hs[t+1] . Wout[o] + bias[o] ----------------
__global__ void esn_out(const float* __restrict__ Wout_w,
                        const float* __restrict__ Wout_b,
                        float* __restrict__ out) {
    const int t   = blockIdx.x;
    const int tid = threadIdx.x;
    const float* h = g_hs + (size_t)(t + 1) * R * Bz;

    const int b = tid & 15;
    const int g = tid >> 4;
    float a0 = 0.f, a1 = 0.f, a2 = 0.f;
    for (int r = g; r < R; r += 16) {
        float hv = __ldg(h + (size_t)r * Bz + b);
        a0 = fmaf(hv, __ldg(Wout_w + r),         a0);
        a1 = fmaf(hv, __ldg(Wout_w + R + r),     a1);
        a2 = fmaf(hv, __ldg(Wout_w + 2 * R + r), a2);
    }
    __shared__ float red[256][3];
    red[tid][0] = a0; red[tid][1] = a1; red[tid][2] = a2;
    __syncthreads();
    if (tid < Bz * NO) {
        int bb = tid / 3, o = tid - bb * 3;
        float sum = 0.f;
        #pragma unroll
        for (int gg = 0; gg < 16; ++gg) sum += red[gg * 16 + bb][o];
        out[((size_t)bb * Tn + t) * 3 + o] = sum + Wout_b[o];
    }
}

// ---------------- launch ----------------
extern "C" void kernel_launch(void* const* d_in, const int* in_sizes, int n_in,
                              void* d_out, int out_size) {
    const float* x      = (const float*)d_in[0];  // [16, 2048, 3]
    const float* Win    = (const float*)d_in[1];  // [2048, 3]
    const float* W      = (const float*)d_in[2];  // [2048, 2048]
    const float* Wout_w = (const float*)d_in[3];  // [3, 2048]
    const float* Wout_b = (const float*)d_in[4];  // [3]
    float* out = (float*)d_out;                   // [16, 2048, 3]

    (void)in_sizes; (void)n_in; (void)out_size;

    build_csr<<<(R * 32 + 255) / 256, 256>>>(W);   // CSR + counter/h0 reset
    esn_steps<<<NBLK, TPB>>>(x, Win);              // 2048 steps, adaptive gather
    esn_out<<<Tn, 256>>>(Wout_w, Wout_b, out);     // readout projection
}